// round 2
// baseline (speedup 1.0000x reference)
#include <cuda_runtime.h>
#include <math.h>

#define Bb 2
#define Tt 16
#define Nn 10000
#define INDIM 128
#define HIDD 256
#define OUTD 128
#define Ee 160000
#define G3 768

// ---- scratch (static device memory; no allocations) ----
__device__ __align__(16) float g_axs[(size_t)Bb*Nn*INDIM]; // agg(x) for current t
__device__ __align__(16) float g_h [Bb*Nn*HIDD];
__device__ __align__(16) float g_ah[Bb*Nn*HIDD];
__device__ __align__(16) float g_gx[(size_t)Bb*Nn*G3];
__device__ __align__(16) float g_gh[(size_t)Bb*Nn*G3];
__device__ __align__(16) float g_Wx[INDIM*G3];  // [Wxr|Wxz|Wxn]
__device__ __align__(16) float g_Wh[HIDD*G3];   // [Whr|Whz|Whn]
__device__ float g_dinv[Nn];
__device__ int   g_deg[Nn];
__device__ int   g_fill[Nn];
__device__ int   g_ptr[Nn+1];
__device__ int   g_csrc[Ee];
__device__ float g_cw[Ee];

// ---- zero state ----
__global__ void k_zero() {
    int i = blockIdx.x*blockDim.x + threadIdx.x;
    if (i < Bb*Nn*HIDD) g_h[i] = 0.f;
    if (i < Nn) { g_deg[i] = 0; g_fill[i] = 0; }
}

// ---- degree histogram (dst) ----
__global__ void k_count(const int* __restrict__ ei) {
    int i = blockIdx.x*blockDim.x + threadIdx.x;
    if (i < Ee) atomicAdd(&g_deg[ei[Ee + i]], 1);
}

// ---- exclusive scan over degrees + dinv (single block) ----
__global__ void k_scan() {
    __shared__ int ssum[1024];
    int tid = threadIdx.x;
    int base = tid * 10;
    int loc[10];
    int s = 0;
    if (tid < 1000) {
        #pragma unroll
        for (int i = 0; i < 10; i++) { loc[i] = g_deg[base+i]; s += loc[i]; }
    }
    ssum[tid] = (tid < 1000) ? s : 0;
    __syncthreads();
    for (int off = 1; off < 1024; off <<= 1) {
        int v = ssum[tid];
        int add = (tid >= off) ? ssum[tid - off] : 0;
        __syncthreads();
        ssum[tid] = v + add;
        __syncthreads();
    }
    if (tid < 1000) {
        int excl = (tid == 0) ? 0 : ssum[tid-1];
        #pragma unroll
        for (int i = 0; i < 10; i++) {
            g_ptr[base+i] = excl;
            excl += loc[i];
            g_dinv[base+i] = rsqrtf((float)(loc[i] + 1)); // +1 self-loop
        }
    }
    if (tid == 0) g_ptr[Nn] = ssum[1023];
}

// ---- CSR fill (sorted by dst) with precomputed edge weight ----
__global__ void k_fill(const int* __restrict__ ei) {
    int i = blockIdx.x*blockDim.x + threadIdx.x;
    if (i < Ee) {
        int s = ei[i], d = ei[Ee + i];
        int pos = g_ptr[d] + atomicAdd(&g_fill[d], 1);
        g_csrc[pos] = s;
        g_cw[pos] = g_dinv[s] * g_dinv[d];
    }
}

// ---- concatenate gate weights ----
__global__ void k_prepw(const float* __restrict__ Wxr, const float* __restrict__ Wxz,
                        const float* __restrict__ Wxn, const float* __restrict__ Whr,
                        const float* __restrict__ Whz, const float* __restrict__ Whn) {
    int i = blockIdx.x*blockDim.x + threadIdx.x;
    const int nx = INDIM * G3;
    const int nh = HIDD * G3;
    if (i < nx) {
        int k = i / G3, j = i % G3;
        g_Wx[i] = (j < 256) ? Wxr[k*256 + j]
                : (j < 512) ? Wxz[k*256 + (j-256)]
                            : Wxn[k*256 + (j-512)];
    } else if (i < nx + nh) {
        int ii = i - nx;
        int k = ii / G3, j = ii % G3;
        g_Wh[ii] = (j < 256) ? Whr[k*256 + j]
                 : (j < 512) ? Whz[k*256 + (j-256)]
                             : Whn[k*256 + (j-512)];
    }
}

// ---- agg over x slice t: one warp per (b, node), 128 dims = 32 lanes x float4 ----
__global__ void k_aggx(const float* __restrict__ x, int t) {
    int node = blockIdx.x*blockDim.y + threadIdx.y;
    if (node >= Nn) return;
    int b = blockIdx.y;
    int lane = threadIdx.x;
    const float* xs = x + ((size_t)b*Tt + t)*Nn*INDIM;
    float* os = g_axs + (size_t)b*Nn*INDIM;
    float dn = g_dinv[node];
    float w0 = dn * dn;
    float4 v = *(const float4*)&xs[node*INDIM + lane*4];
    float4 acc = make_float4(w0*v.x, w0*v.y, w0*v.z, w0*v.w);
    int p1 = g_ptr[node+1];
    for (int p = g_ptr[node]; p < p1; p++) {
        int s = g_csrc[p]; float w = g_cw[p];
        float4 u = *(const float4*)&xs[s*INDIM + lane*4];
        acc.x += w*u.x; acc.y += w*u.y; acc.z += w*u.z; acc.w += w*u.w;
    }
    *(float4*)&os[node*INDIM + lane*4] = acc;
}

// ---- agg over h: one warp per (b, node), 256 dims = 32 lanes x 2 float4 ----
__global__ void k_aggh() {
    int node = blockIdx.x*blockDim.y + threadIdx.y;
    if (node >= Nn) return;
    int b = blockIdx.y;
    int lane = threadIdx.x;
    const float* hs = g_h + (size_t)b*Nn*HIDD;
    float* os = g_ah + (size_t)b*Nn*HIDD;
    float dn = g_dinv[node];
    float w0 = dn * dn;
    float4 v0 = *(const float4*)&hs[node*HIDD + lane*4];
    float4 v1 = *(const float4*)&hs[node*HIDD + 128 + lane*4];
    float4 a0 = make_float4(w0*v0.x, w0*v0.y, w0*v0.z, w0*v0.w);
    float4 a1 = make_float4(w0*v1.x, w0*v1.y, w0*v1.z, w0*v1.w);
    int p1 = g_ptr[node+1];
    for (int p = g_ptr[node]; p < p1; p++) {
        int s = g_csrc[p]; float w = g_cw[p];
        float4 u0 = *(const float4*)&hs[s*HIDD + lane*4];
        float4 u1 = *(const float4*)&hs[s*HIDD + 128 + lane*4];
        a0.x += w*u0.x; a0.y += w*u0.y; a0.z += w*u0.z; a0.w += w*u0.w;
        a1.x += w*u1.x; a1.y += w*u1.y; a1.z += w*u1.z; a1.w += w*u1.w;
    }
    *(float4*)&os[node*HIDD + lane*4] = a0;
    *(float4*)&os[node*HIDD + 128 + lane*4] = a1;
}

// ---- fp32 SIMT GEMM: C[b] = A[b] @ Bw (+bias), tiles 128x64x16, 8x4/thread ----
__global__ void __launch_bounds__(256)
k_gemm(const float* __restrict__ A, long aStride,
       const float* __restrict__ Bw,
       float* __restrict__ C, long cStride,
       int K, int Ncols, const float* __restrict__ bias) {
    __shared__ float As[16][132];
    __shared__ float Bs[16][64];
    const float* Ab = A + (long)blockIdx.z * aStride;
    float* Cb = C + (long)blockIdx.z * cStride;
    int row0 = blockIdx.y * 128;
    int col0 = blockIdx.x * 64;
    int tid = threadIdx.x;
    int tx = tid & 15, ty = tid >> 4;
    float acc[8][4];
    #pragma unroll
    for (int i = 0; i < 8; i++)
        #pragma unroll
        for (int j = 0; j < 4; j++) acc[i][j] = 0.f;

    for (int k0 = 0; k0 < K; k0 += 16) {
        #pragma unroll
        for (int l = 0; l < 2; l++) {
            int f = tid + l*256;
            int m = f >> 2, kq = (f & 3) << 2;
            int row = row0 + m;
            float4 v = make_float4(0.f, 0.f, 0.f, 0.f);
            if (row < Nn) v = *(const float4*)&Ab[(long)row*K + k0 + kq];
            As[kq+0][m] = v.x; As[kq+1][m] = v.y; As[kq+2][m] = v.z; As[kq+3][m] = v.w;
        }
        {
            int kk = tid >> 4, nq = (tid & 15) << 2;
            *(float4*)&Bs[kk][nq] = *(const float4*)&Bw[(long)(k0+kk)*Ncols + col0 + nq];
        }
        __syncthreads();
        #pragma unroll
        for (int k = 0; k < 16; k++) {
            float a[8];
            #pragma unroll
            for (int i = 0; i < 8; i++) a[i] = As[k][ty*8 + i];
            float4 b4 = *(float4*)&Bs[k][tx*4];
            #pragma unroll
            for (int i = 0; i < 8; i++) {
                acc[i][0] += a[i]*b4.x; acc[i][1] += a[i]*b4.y;
                acc[i][2] += a[i]*b4.z; acc[i][3] += a[i]*b4.w;
            }
        }
        __syncthreads();
    }
    float4 bv = make_float4(0.f, 0.f, 0.f, 0.f);
    if (bias) bv = *(const float4*)&bias[col0 + tx*4];
    #pragma unroll
    for (int i = 0; i < 8; i++) {
        int row = row0 + ty*8 + i;
        if (row < Nn) {
            float4 o = make_float4(acc[i][0]+bv.x, acc[i][1]+bv.y,
                                   acc[i][2]+bv.z, acc[i][3]+bv.w);
            *(float4*)&Cb[(long)row*Ncols + col0 + tx*4] = o;
        }
    }
}

// ---- GRU gates + state update ----
__global__ void k_gates(const float* __restrict__ bxr, const float* __restrict__ bhr,
                        const float* __restrict__ bxz, const float* __restrict__ bhz,
                        const float* __restrict__ bxn, const float* __restrict__ bhn) {
    int i = blockIdx.x*blockDim.x + threadIdx.x;
    if (i >= Bb*Nn*HIDD) return;
    int j = i & 255;
    int bn = i >> 8;
    long g = (long)bn * G3;
    float r = 1.f / (1.f + expf(-(g_gx[g+j]     + g_gh[g+j]     + bxr[j] + bhr[j])));
    float z = 1.f / (1.f + expf(-(g_gx[g+256+j] + g_gh[g+256+j] + bxz[j] + bhz[j])));
    float nn = tanhf(g_gx[g+512+j] + bxn[j] + r * (g_gh[g+512+j] + bhn[j]));
    float h = g_h[i];
    g_h[i] = (1.f - z) * h + z * nn;
}

extern "C" void kernel_launch(void* const* d_in, const int* in_sizes, int n_in,
                              void* d_out, int out_size) {
    const float* x   = (const float*)d_in[0];
    const int*   ei  = (const int*)  d_in[1];
    const float* Wxr = (const float*)d_in[2];  const float* bxr = (const float*)d_in[3];
    const float* Whr = (const float*)d_in[4];  const float* bhr = (const float*)d_in[5];
    const float* Wxz = (const float*)d_in[6];  const float* bxz = (const float*)d_in[7];
    const float* Whz = (const float*)d_in[8];  const float* bhz = (const float*)d_in[9];
    const float* Wxn = (const float*)d_in[10]; const float* bxn = (const float*)d_in[11];
    const float* Whn = (const float*)d_in[12]; const float* bhn = (const float*)d_in[13];
    const float* Wfc = (const float*)d_in[14]; const float* bfc = (const float*)d_in[15];
    float* out = (float*)d_out;

    float *p_axs, *p_ah, *p_gx, *p_gh, *p_h, *p_Wx, *p_Wh;
    cudaGetSymbolAddress((void**)&p_axs, g_axs);
    cudaGetSymbolAddress((void**)&p_ah, g_ah);
    cudaGetSymbolAddress((void**)&p_gx, g_gx);
    cudaGetSymbolAddress((void**)&p_gh, g_gh);
    cudaGetSymbolAddress((void**)&p_h,  g_h);
    cudaGetSymbolAddress((void**)&p_Wx, g_Wx);
    cudaGetSymbolAddress((void**)&p_Wh, g_Wh);

    k_zero<<<(Bb*Nn*HIDD + 255)/256, 256>>>();
    k_count<<<(Ee + 255)/256, 256>>>(ei);
    k_scan<<<1, 1024>>>();
    k_fill<<<(Ee + 255)/256, 256>>>(ei);
    k_prepw<<<((INDIM + HIDD)*G3 + 255)/256, 256>>>(Wxr, Wxz, Wxn, Whr, Whz, Whn);

    dim3 bagg(32, 4);
    dim3 gagg((Nn + 3)/4, Bb);
    dim3 gg(G3/64, (Nn + 127)/128, Bb);
    dim3 gfc(OUTD/64, (Nn + 127)/128, Bb);

    for (int t = 0; t < Tt; t++) {
        // AXS = agg(x_t)
        k_aggx<<<gagg, bagg>>>(x, t);
        // GX = AXS @ Wx
        k_gemm<<<gg, 256>>>(p_axs, (long)Nn*INDIM,
                            p_Wx, p_gx, (long)Nn*G3, INDIM, G3, nullptr);
        // AH = agg(h)
        k_aggh<<<gagg, bagg>>>();
        // GH = AH @ Wh
        k_gemm<<<gg, 256>>>(p_ah, (long)Nn*HIDD,
                            p_Wh, p_gh, (long)Nn*G3, HIDD, G3, nullptr);
        // gates + h update
        k_gates<<<(Bb*Nn*HIDD + 255)/256, 256>>>(bxr, bhr, bxz, bhz, bxn, bhn);
        // out_t = h @ Wfc + bfc
        k_gemm<<<gfc, 256>>>(p_h, (long)Nn*HIDD,
                             Wfc, out + (long)t*Nn*OUTD, (long)Tt*Nn*OUTD,
                             HIDD, OUTD, bfc);
    }
}